// round 15
// baseline (speedup 1.0000x reference)
#include <cuda_runtime.h>
#include <cuda_bf16.h>
#include <cstdint>

#define MAX_N 100000
#define MAX_E 500000
#define DIM     160
#define NS       64
#define NV       32
#define USTRIDE 516   // U row stride (floats); %32==4 -> conflict-free A frags
#define CAP      32   // per-node edge-list capacity (Poisson(5): P(>=32)~3e-17)
#define NPC      32   // nodes per CTA (node_update): 2 M-tiles per warp

typedef unsigned long long ull;

// ---- device scratch (no allocs allowed) ----
// g_cnt is zero-initialized at module load; node_update re-zeroes it each run.
__device__ int g_cnt[MAX_N];                        // per-node degree
__device__ int g_list[MAX_N * CAP];                 // per-node edge ids
__device__ __align__(16) float g_msg[MAX_N * DIM];  // gathered message sums
// Weights pre-packed in m16n8k8 B-fragment order, tf32-rounded.
__device__ __align__(16) ull g_Bs[24 * 12 * 32];   // s-path  K=192, O=96
__device__ __align__(16) ull g_B1[16 * 4 * 32];    // v1      K=128, O=32
__device__ __align__(16) ull g_B2[ 8 * 4 * 32];    // v2      K=64,  O=32

__device__ __forceinline__ unsigned tf32r(float x) {
    unsigned r; asm("cvt.rna.tf32.f32 %0, %1;" : "=r"(r) : "f"(x)); return r;
}
__device__ __forceinline__ ull packtf(float lo, float hi) {
    return (ull)tf32r(lo) | ((ull)tf32r(hi) << 32);
}
__device__ __forceinline__ float tf32f(float x) {
    return __uint_as_float(tf32r(x));
}

#define MMA8(d, a0, a1, a2, a3, bb)                                         \
    asm("mma.sync.aligned.m16n8k8.row.col.f32.tf32.tf32.f32 "               \
        "{%0,%1,%2,%3}, {%4,%5,%6,%7}, {%8,%9}, {%0,%1,%2,%3};"             \
        : "+f"(d[0]), "+f"(d[1]), "+f"(d[2]), "+f"(d[3])                    \
        : "r"(a0), "r"(a1), "r"(a2), "r"(a3),                               \
          "r"((unsigned)(bb)), "r"((unsigned)((bb) >> 32)))

// ---------------------------------------------------------------------------
// Combined-weight element generators (fold all norm scalars + tp vectors)
// ---------------------------------------------------------------------------
__device__ __forceinline__ float comb_s(int u, int o,
                                        const float* Wls, const float* W000,
                                        const float* W110, const float* w00,
                                        const float* w11) {
    const float inv_fan = rsqrtf(96.f);
    const float inv2 = rsqrtf(2.f);
    if (u < 64)  return Wls[u * 96 + o] * inv_fan * w00[u];
    if (u < 96)  return Wls[u * 96 + o] * inv_fan * w11[u - 64];
    if (u < 160) return W000[(u - 96) * 96 + o] * inv2 * rsqrtf(64.f);
    return W110[(u - 160) * 96 + o] * inv2 * rsqrtf(32.f);
}
__device__ __forceinline__ float comb_1(int u, int o,
                                        const float* Wlv, const float* W011,
                                        const float* w01) {
    const float inv_fan = rsqrtf(96.f);
    const float inv2 = rsqrtf(2.f);
    if (u < 64) return Wlv[u * 32 + o] * inv_fan * w01[u];
    return W011[(u - 64) * 32 + o] * inv2 * rsqrtf(64.f);
}
__device__ __forceinline__ float comb_2(int u, int o,
                                        const float* Wlv, const float* W101,
                                        const float* w10) {
    const float inv_fan = rsqrtf(96.f);
    const float inv2 = rsqrtf(2.f);
    if (u < 32) return Wlv[(64 + u) * 32 + o] * inv_fan * w10[u];
    return W101[(u - 32) * 32 + o] * inv2 * rsqrtf(32.f);
}

// ---------------------------------------------------------------------------
// Kernel 1: weight packing FUSED with edge binning (independent ranges).
// ---------------------------------------------------------------------------
__global__ void prep_and_bin(const float* __restrict__ Wls,
                             const float* __restrict__ Wlv,
                             const float* __restrict__ W000,
                             const float* __restrict__ W110,
                             const float* __restrict__ W011,
                             const float* __restrict__ W101,
                             const float* __restrict__ w00,
                             const float* __restrict__ w01,
                             const float* __restrict__ w10,
                             const float* __restrict__ w11,
                             const int*   __restrict__ eidx,
                             int E)
{
    int i = blockIdx.x * blockDim.x + threadIdx.x;
    const int NSZ = 24 * 12 * 32;
    const int V1Z = 16 * 4 * 32;
    const int V2Z = 8 * 4 * 32;
    const int WTOT = NSZ + V1Z + V2Z;
    if (i < NSZ) {
        int kb = i / (12 * 32), r = i % (12 * 32), nb = r / 32, lane = r % 32;
        int k = kb * 8 + (lane & 3), n = nb * 8 + (lane >> 2);
        g_Bs[i] = packtf(comb_s(k, n, Wls, W000, W110, w00, w11),
                         comb_s(k + 4, n, Wls, W000, W110, w00, w11));
    } else if (i < NSZ + V1Z) {
        int j = i - NSZ;
        int kb = j / (4 * 32), r = j % (4 * 32), nb = r / 32, lane = r % 32;
        int k = kb * 8 + (lane & 3), n = nb * 8 + (lane >> 2);
        g_B1[j] = packtf(comb_1(k, n, Wlv, W011, w01),
                         comb_1(k + 4, n, Wlv, W011, w01));
    } else if (i < WTOT) {
        int j = i - NSZ - V1Z;
        int kb = j / (4 * 32), r = j % (4 * 32), nb = r / 32, lane = r % 32;
        int k = kb * 8 + (lane & 3), n = nb * 8 + (lane >> 2);
        g_B2[j] = packtf(comb_2(k, n, Wlv, W101, w10),
                         comb_2(k + 4, n, Wlv, W101, w10));
    } else {
        int e = i - WTOT;
        if (e < E) {
            int dst = __ldg(eidx + E + e);   // edge_index row 1 = destination
            int pos = atomicAdd(&g_cnt[dst], 1);
            if (pos < CAP) g_list[dst * CAP + pos] = e;
        }
    }
}

// ---------------------------------------------------------------------------
// Kernel 2: atomic-free gather, one float4 chunk per thread, edge-unroll-4.
// ---------------------------------------------------------------------------
__global__ void gather_msg(const float4* __restrict__ em, int N)
{
    int i = blockIdx.x * blockDim.x + threadIdx.x;
    if (i >= N * 40) return;
    int n = i / 40;
    int j = i - n * 40;
    int deg = g_cnt[n];
    if (deg > CAP) deg = CAP;
    const int* lst = g_list + n * CAP;
    float4 s = make_float4(0.f, 0.f, 0.f, 0.f);
    int k = 0;
    for (; k + 4 <= deg; k += 4) {
        int e0 = __ldg(lst + k);
        int e1 = __ldg(lst + k + 1);
        int e2 = __ldg(lst + k + 2);
        int e3 = __ldg(lst + k + 3);
        float4 v0 = __ldcs(em + (size_t)e0 * 40 + j);
        float4 v1 = __ldcs(em + (size_t)e1 * 40 + j);
        float4 v2 = __ldcs(em + (size_t)e2 * 40 + j);
        float4 v3 = __ldcs(em + (size_t)e3 * 40 + j);
        s.x += (v0.x + v1.x) + (v2.x + v3.x);
        s.y += (v0.y + v1.y) + (v2.y + v3.y);
        s.z += (v0.z + v1.z) + (v2.z + v3.z);
        s.w += (v0.w + v1.w) + (v2.w + v3.w);
    }
    if (k + 2 <= deg) {
        int e0 = __ldg(lst + k);
        int e1 = __ldg(lst + k + 1);
        float4 v0 = __ldcs(em + (size_t)e0 * 40 + j);
        float4 v1 = __ldcs(em + (size_t)e1 * 40 + j);
        s.x += v0.x + v1.x; s.y += v0.y + v1.y;
        s.z += v0.z + v1.z; s.w += v0.w + v1.w;
        k += 2;
    }
    if (k < deg) {
        int e = __ldg(lst + k);
        float4 v = __ldcs(em + (size_t)e * 40 + j);
        s.x += v.x; s.y += v.y; s.z += v.z; s.w += v.w;
    }
    reinterpret_cast<float4*>(g_msg)[i] = s;
}

// ---------------------------------------------------------------------------
// Kernel 3: per-node update (m16n8k8 tf32), warp grid = N-half x K-half,
// TWO M-tiles per warp (32 nodes/CTA): each B fragment is loaded once per
// CTA and feeds 32 M-rows -> weight wavefronts per node halve vs NPC=16.
// 128 threads = 4 warps, 66 KB smem -> 3 CTAs/SM.
// ---------------------------------------------------------------------------
__global__ void __launch_bounds__(128, 3)
node_update(const float* __restrict__ feats,
            const float* __restrict__ attrs,
            float*       __restrict__ out,
            int N)
{
    extern __shared__ __align__(16) float sm[];
    float* sU  = sm;                    // NPC * USTRIDE (reused as sred later)
    float* sAv = sm + NPC * USTRIDE;    // NPC * 3

    const float rs5  = 0.44721359549995794f;  // 1/sqrt(5)
    const float inv3 = 0.5773502691896258f;   // 1/sqrt(3)

    const int t    = threadIdx.x;
    const int base = blockIdx.x * NPC;

    // ---- prologue: build tf32-rounded U (4 threads per node, 32 nodes) ----
    {
        int i  = t >> 2;
        int t4 = t & 3;
        int n  = base + i;
        float* u = sU + i * USTRIDE;
        if (n < N) {
            float a0  = __ldg(attrs + n * 4 + 0);
            float av0 = __ldg(attrs + n * 4 + 1);
            float av1 = __ldg(attrs + n * 4 + 2);
            float av2 = __ldg(attrs + n * 4 + 3);
            if (t4 == 0) {
                sAv[i * 3 + 0] = av0; sAv[i * 3 + 1] = av1; sAv[i * 3 + 2] = av2;
                g_cnt[n] = 0;   // reset degree counter for the next run
            }
            const float* mrow = g_msg + (size_t)n * DIM;
            const float* frow = feats + (size_t)n * DIM;
            #pragma unroll
            for (int k = t4; k < 64; k += 4) {
                float ms = mrow[k] * rs5;
                float xs = __ldcs(frow + k);
                u[k]       = tf32f(a0 * ms);
                u[96 + k]  = tf32f(a0 * xs);
                u[192 + k] = tf32f(ms);
                u[256 + k] = tf32f(xs);
            }
            #pragma unroll
            for (int k = t4; k < 32; k += 4) {
                float m0 = mrow[64 + k * 3 + 0] * rs5;
                float m1 = mrow[64 + k * 3 + 1] * rs5;
                float m2 = mrow[64 + k * 3 + 2] * rs5;
                float x0 = __ldcs(frow + 64 + k * 3 + 0);
                float x1 = __ldcs(frow + 64 + k * 3 + 1);
                float x2 = __ldcs(frow + 64 + k * 3 + 2);
                u[64 + k]  = tf32f((m0 * av0 + m1 * av1 + m2 * av2) * inv3);
                u[160 + k] = tf32f((x0 * av0 + x1 * av1 + x2 * av2) * inv3);
                u[320 + k] = tf32f(a0 * m0);
                u[384 + k] = tf32f(a0 * m1);
                u[448 + k] = tf32f(a0 * m2);
                u[352 + k] = tf32f(a0 * x0);
                u[416 + k] = tf32f(a0 * x1);
                u[480 + k] = tf32f(a0 * x2);
            }
        } else {
            #pragma unroll
            for (int k = t4; k < 512; k += 4) u[k] = 0.f;
            if (t4 == 0) { sAv[i*3] = 0.f; sAv[i*3+1] = 0.f; sAv[i*3+2] = 0.f; }
        }
    }
    __syncthreads();

    const int lane = t & 31;
    const int w    = t >> 5;
    const int nh   = w & 1;          // N half (0 or 1)
    const int kh   = w >> 1;         // K half (0 or 1)
    const int gid  = lane >> 2;
    const int tid  = lane & 3;
    const int rA0  = gid * USTRIDE;                 // M-tile 0 rows 0-7
    const int rB0  = rA0 + 8 * USTRIDE;             // M-tile 0 rows 8-15
    const int rA1  = rA0 + 16 * USTRIDE;            // M-tile 1 rows 16-23
    const int rB1  = rA0 + 24 * USTRIDE;            // M-tile 1 rows 24-31
    const unsigned* uU = (const unsigned*)sU;

    // ---- s-path: 6 N-tiles x 2 M-tiles, K-half kb in [12kh, 12kh+12) ----
    float sd[2][6][4];
    #pragma unroll
    for (int m = 0; m < 2; ++m)
        #pragma unroll
        for (int j = 0; j < 6; ++j)
            { sd[m][j][0]=0.f; sd[m][j][1]=0.f; sd[m][j][2]=0.f; sd[m][j][3]=0.f; }
    #pragma unroll 2
    for (int kk = 0; kk < 12; ++kk) {
        int kb = 12 * kh + kk;
        int kc = kb * 8 + tid;
        unsigned a00 = uU[rA0 + kc],     a01 = uU[rB0 + kc];
        unsigned a02 = uU[rA0 + kc + 4], a03 = uU[rB0 + kc + 4];
        unsigned a10 = uU[rA1 + kc],     a11 = uU[rB1 + kc];
        unsigned a12 = uU[rA1 + kc + 4], a13 = uU[rB1 + kc + 4];
        #pragma unroll
        for (int j = 0; j < 6; ++j) {
            int tile = 2 * nh + (j & 1) + 4 * (j >> 1);
            ull b = __ldg(g_Bs + (kb * 12 + tile) * 32 + lane);
            MMA8(sd[0][j], a00, a01, a02, a03, b);
            MMA8(sd[1][j], a10, a11, a12, a13, b);
        }
    }

    // ---- v1: tiles {2nh, 2nh+1} x 2 M-tiles, kb in [8kh, 8kh+8) ----
    float vd[2][2][4];
    #pragma unroll
    for (int m = 0; m < 2; ++m)
        #pragma unroll
        for (int j = 0; j < 2; ++j)
            { vd[m][j][0]=0.f; vd[m][j][1]=0.f; vd[m][j][2]=0.f; vd[m][j][3]=0.f; }
    #pragma unroll 2
    for (int kk = 0; kk < 8; ++kk) {
        int kb = 8 * kh + kk;
        int kc = 192 + kb * 8 + tid;
        unsigned a00 = uU[rA0 + kc],     a01 = uU[rB0 + kc];
        unsigned a02 = uU[rA0 + kc + 4], a03 = uU[rB0 + kc + 4];
        unsigned a10 = uU[rA1 + kc],     a11 = uU[rB1 + kc];
        unsigned a12 = uU[rA1 + kc + 4], a13 = uU[rB1 + kc + 4];
        #pragma unroll
        for (int j = 0; j < 2; ++j) {
            ull b = __ldg(g_B1 + (kb * 4 + 2 * nh + j) * 32 + lane);
            MMA8(vd[0][j], a00, a01, a02, a03, b);
            MMA8(vd[1][j], a10, a11, a12, a13, b);
        }
    }

    // ---- v2: tiles {2nh,2nh+1} x 3 ch x 2 M-tiles, kb in [4kh, 4kh+4) ----
    float pd[2][2][3][4];
    #pragma unroll
    for (int m = 0; m < 2; ++m)
        #pragma unroll
        for (int j = 0; j < 2; ++j)
            #pragma unroll
            for (int c = 0; c < 3; ++c)
                { pd[m][j][c][0]=0.f; pd[m][j][c][1]=0.f;
                  pd[m][j][c][2]=0.f; pd[m][j][c][3]=0.f; }
    #pragma unroll 2
    for (int kk = 0; kk < 4; ++kk) {
        int kb = 4 * kh + kk;
        ull b0 = __ldg(g_B2 + (kb * 4 + 2 * nh) * 32 + lane);
        ull b1 = __ldg(g_B2 + (kb * 4 + 2 * nh + 1) * 32 + lane);
        #pragma unroll
        for (int c = 0; c < 3; ++c) {
            int kc = 320 + 64 * c + kb * 8 + tid;
            unsigned a00 = uU[rA0 + kc],     a01 = uU[rB0 + kc];
            unsigned a02 = uU[rA0 + kc + 4], a03 = uU[rB0 + kc + 4];
            unsigned a10 = uU[rA1 + kc],     a11 = uU[rB1 + kc];
            unsigned a12 = uU[rA1 + kc + 4], a13 = uU[rB1 + kc + 4];
            MMA8(pd[0][0][c], a00, a01, a02, a03, b0);
            MMA8(pd[0][1][c], a00, a01, a02, a03, b1);
            MMA8(pd[1][0][c], a10, a11, a12, a13, b0);
            MMA8(pd[1][1][c], a10, a11, a12, a13, b1);
        }
    }

    // ---- cross-warp K reduction: kh=1 -> shared -> kh=0 adds ----
    // sred layout: [(nh*2 + mt)][j 0..55][lane], reuses sU region.
    __syncthreads();
    if (kh == 1) {
        #pragma unroll
        for (int m = 0; m < 2; ++m) {
            float* sred = sm + (nh * 2 + m) * 56 * 32;
            #pragma unroll
            for (int j = 0; j < 6; ++j)
                #pragma unroll
                for (int q = 0; q < 4; ++q)
                    sred[(j * 4 + q) * 32 + lane] = sd[m][j][q];
            #pragma unroll
            for (int j = 0; j < 2; ++j)
                #pragma unroll
                for (int q = 0; q < 4; ++q)
                    sred[(24 + j * 4 + q) * 32 + lane] = vd[m][j][q];
            #pragma unroll
            for (int j = 0; j < 2; ++j)
                #pragma unroll
                for (int c = 0; c < 3; ++c)
                    #pragma unroll
                    for (int q = 0; q < 4; ++q)
                        sred[(32 + (j * 3 + c) * 4 + q) * 32 + lane] = pd[m][j][c][q];
        }
    }
    __syncthreads();
    if (kh == 1) return;

    #pragma unroll
    for (int m = 0; m < 2; ++m) {
        const float* sred = sm + (nh * 2 + m) * 56 * 32;
        #pragma unroll
        for (int j = 0; j < 6; ++j)
            #pragma unroll
            for (int q = 0; q < 4; ++q)
                sd[m][j][q] += sred[(j * 4 + q) * 32 + lane];
        #pragma unroll
        for (int j = 0; j < 2; ++j)
            #pragma unroll
            for (int q = 0; q < 4; ++q)
                vd[m][j][q] += sred[(24 + j * 4 + q) * 32 + lane];
        #pragma unroll
        for (int j = 0; j < 2; ++j)
            #pragma unroll
            for (int c = 0; c < 3; ++c)
                #pragma unroll
                for (int q = 0; q < 4; ++q)
                    pd[m][j][c][q] += sred[(32 + (j * 3 + c) * 4 + q) * 32 + lane];
    }

    // ---- epilogue (kh=0 warps): all combining in registers ----
    const int nvalid = N - base;
    #pragma unroll
    for (int m = 0; m < 2; ++m) {
        #pragma unroll
        for (int r = 0; r < 2; ++r) {
            int slot = m * 16 + gid + 8 * r;
            if (slot < nvalid) {
                float* orow = out + (size_t)(base + slot) * DIM;
                #pragma unroll
                for (int jj = 0; jj < 2; ++jj) {
                    float x0 = sd[m][jj][2*r],   x1 = sd[m][jj][2*r+1];
                    float y0 = sd[m][2+jj][2*r], y1 = sd[m][2+jj][2*r+1];
                    *(float2*)(orow + 8 * (2 * nh + jj) + 2 * tid) =
                        make_float2(x0 / (1.f + __expf(-x0)),
                                    x1 / (1.f + __expf(-x1)));
                    *(float2*)(orow + 32 + 8 * (2 * nh + jj) + 2 * tid) =
                        make_float2(y0 / (1.f + __expf(-y0)),
                                    y1 / (1.f + __expf(-y1)));
                }
                float av0 = sAv[slot * 3 + 0];
                float av1 = sAv[slot * 3 + 1];
                float av2 = sAv[slot * 3 + 2];
                #pragma unroll
                for (int jj = 0; jj < 2; ++jj) {
                    float g0 = 1.f / (1.f + __expf(-sd[m][4+jj][2*r]));
                    float g1 = 1.f / (1.f + __expf(-sd[m][4+jj][2*r+1]));
                    float v0 = vd[m][jj][2*r], v1 = vd[m][jj][2*r+1];
                    float j0c0 = g0 * fmaf(v0, av0, pd[m][jj][0][2*r]);
                    float j0c1 = g0 * fmaf(v0, av1, pd[m][jj][1][2*r]);
                    float j0c2 = g0 * fmaf(v0, av2, pd[m][jj][2][2*r]);
                    float j1c0 = g1 * fmaf(v1, av0, pd[m][jj][0][2*r+1]);
                    float j1c1 = g1 * fmaf(v1, av1, pd[m][jj][1][2*r+1]);
                    float j1c2 = g1 * fmaf(v1, av2, pd[m][jj][2][2*r+1]);
                    float* vout = orow + NS + (8 * (2 * nh + jj) + 2 * tid) * 3;
                    *(float2*)(vout + 0) = make_float2(j0c0, j0c1);
                    *(float2*)(vout + 2) = make_float2(j0c2, j1c0);
                    *(float2*)(vout + 4) = make_float2(j1c1, j1c2);
                }
            }
        }
    }
}

// ---------------------------------------------------------------------------
extern "C" void kernel_launch(void* const* d_in, const int* in_sizes, int n_in,
                              void* d_out, int out_size)
{
    const float* feats = (const float*)d_in[0];
    const float* attrs = (const float*)d_in[1];
    const float* emsg  = (const float*)d_in[2];
    const int*   eidx  = (const int*)  d_in[3];
    const float* w00   = (const float*)d_in[4];
    const float* w01   = (const float*)d_in[5];
    const float* w10   = (const float*)d_in[6];
    const float* w11   = (const float*)d_in[7];
    const float* Wls   = (const float*)d_in[8];
    const float* Wlv   = (const float*)d_in[9];
    const float* W000  = (const float*)d_in[10];
    const float* W110  = (const float*)d_in[11];
    const float* W011  = (const float*)d_in[12];
    const float* W101  = (const float*)d_in[13];

    int N = in_sizes[0] / DIM;
    int E = in_sizes[2] / DIM;

    const int smem_bytes = NPC * USTRIDE * 4 + NPC * 3 * 4;  // 66432
    cudaFuncSetAttribute(node_update,
                         cudaFuncAttributeMaxDynamicSharedMemorySize, smem_bytes);

    // 1. weight packing + edge binning (fused; counters already zero)
    int total1 = 24 * 12 * 32 + 16 * 4 * 32 + 8 * 4 * 32 + E;
    prep_and_bin<<<(total1 + 255) / 256, 256>>>(
        Wls, Wlv, W000, W110, W011, W101, w00, w01, w10, w11, eidx, E);

    // 2. gather (1 chunk/thread, edge-unroll-4)
    int gthreads = N * 40;
    gather_msg<<<(gthreads + 511) / 512, 512>>>((const float4*)emsg, N);

    // 3. node update (also re-zeroes g_cnt for the next run)
    int blocks = (N + NPC - 1) / NPC;
    node_update<<<blocks, 128, smem_bytes>>>(feats, attrs, (float*)d_out, N);
}

// round 16
// speedup vs baseline: 1.1027x; 1.1027x over previous
#include <cuda_runtime.h>
#include <cuda_bf16.h>
#include <cstdint>

#define MAX_N 100000
#define MAX_E 500000
#define DIM     160
#define NS       64
#define NV       32
#define USTRIDE 516   // U row stride (floats); %32==4 -> conflict-free frags
#define CAP      32   // per-node edge-list capacity (Poisson(5): P(>=32)~3e-17)
#define NPC      16   // nodes per CTA (node_update)

typedef unsigned long long ull;

// ---- device scratch (no allocs allowed) ----
// g_cnt is zero-initialized at module load; node_update re-zeroes it each run.
__device__ int g_cnt[MAX_N];                        // per-node degree
__device__ int g_list[MAX_N * CAP];                 // per-node edge ids
__device__ __align__(16) float g_msg[MAX_N * DIM];  // gathered message sums
// Weights pre-packed in m16n8k8 B-fragment order, tf32-rounded.
__device__ __align__(16) ull g_Bs[24 * 12 * 32];   // s-path  K=192, O=96
__device__ __align__(16) ull g_B1[16 * 4 * 32];    // v1      K=128, O=32
__device__ __align__(16) ull g_B2[ 8 * 4 * 32];    // v2      K=64,  O=32

__device__ __forceinline__ unsigned tf32r(float x) {
    unsigned r; asm("cvt.rna.tf32.f32 %0, %1;" : "=r"(r) : "f"(x)); return r;
}
__device__ __forceinline__ ull packtf(float lo, float hi) {
    return (ull)tf32r(lo) | ((ull)tf32r(hi) << 32);
}
__device__ __forceinline__ float tf32f(float x) {
    return __uint_as_float(tf32r(x));
}

#define MMA8(d, a0, a1, a2, a3, bb)                                         \
    asm("mma.sync.aligned.m16n8k8.row.col.f32.tf32.tf32.f32 "               \
        "{%0,%1,%2,%3}, {%4,%5,%6,%7}, {%8,%9}, {%0,%1,%2,%3};"             \
        : "+f"(d[0]), "+f"(d[1]), "+f"(d[2]), "+f"(d[3])                    \
        : "r"(a0), "r"(a1), "r"(a2), "r"(a3),                               \
          "r"((unsigned)(bb)), "r"((unsigned)((bb) >> 32)))

// One LDSM.x4 loads the full 16x8 tf32 A fragment (as 16x16 b16).
#define LDSM4(a0, a1, a2, a3, addr)                                         \
    asm volatile("ldmatrix.sync.aligned.m8n8.x4.shared.b16 "                \
                 "{%0,%1,%2,%3}, [%4];"                                     \
                 : "=r"(a0), "=r"(a1), "=r"(a2), "=r"(a3) : "r"(addr))

// ---------------------------------------------------------------------------
// Combined-weight element generators (fold all norm scalars + tp vectors)
// ---------------------------------------------------------------------------
__device__ __forceinline__ float comb_s(int u, int o,
                                        const float* Wls, const float* W000,
                                        const float* W110, const float* w00,
                                        const float* w11) {
    const float inv_fan = rsqrtf(96.f);
    const float inv2 = rsqrtf(2.f);
    if (u < 64)  return Wls[u * 96 + o] * inv_fan * w00[u];
    if (u < 96)  return Wls[u * 96 + o] * inv_fan * w11[u - 64];
    if (u < 160) return W000[(u - 96) * 96 + o] * inv2 * rsqrtf(64.f);
    return W110[(u - 160) * 96 + o] * inv2 * rsqrtf(32.f);
}
__device__ __forceinline__ float comb_1(int u, int o,
                                        const float* Wlv, const float* W011,
                                        const float* w01) {
    const float inv_fan = rsqrtf(96.f);
    const float inv2 = rsqrtf(2.f);
    if (u < 64) return Wlv[u * 32 + o] * inv_fan * w01[u];
    return W011[(u - 64) * 32 + o] * inv2 * rsqrtf(64.f);
}
__device__ __forceinline__ float comb_2(int u, int o,
                                        const float* Wlv, const float* W101,
                                        const float* w10) {
    const float inv_fan = rsqrtf(96.f);
    const float inv2 = rsqrtf(2.f);
    if (u < 32) return Wlv[(64 + u) * 32 + o] * inv_fan * w10[u];
    return W101[(u - 32) * 32 + o] * inv2 * rsqrtf(32.f);
}

// ---------------------------------------------------------------------------
// Kernel 1: weight packing FUSED with edge binning (independent ranges).
// ---------------------------------------------------------------------------
__global__ void prep_and_bin(const float* __restrict__ Wls,
                             const float* __restrict__ Wlv,
                             const float* __restrict__ W000,
                             const float* __restrict__ W110,
                             const float* __restrict__ W011,
                             const float* __restrict__ W101,
                             const float* __restrict__ w00,
                             const float* __restrict__ w01,
                             const float* __restrict__ w10,
                             const float* __restrict__ w11,
                             const int*   __restrict__ eidx,
                             int E)
{
    int i = blockIdx.x * blockDim.x + threadIdx.x;
    const int NSZ = 24 * 12 * 32;
    const int V1Z = 16 * 4 * 32;
    const int V2Z = 8 * 4 * 32;
    const int WTOT = NSZ + V1Z + V2Z;
    if (i < NSZ) {
        int kb = i / (12 * 32), r = i % (12 * 32), nb = r / 32, lane = r % 32;
        int k = kb * 8 + (lane & 3), n = nb * 8 + (lane >> 2);
        g_Bs[i] = packtf(comb_s(k, n, Wls, W000, W110, w00, w11),
                         comb_s(k + 4, n, Wls, W000, W110, w00, w11));
    } else if (i < NSZ + V1Z) {
        int j = i - NSZ;
        int kb = j / (4 * 32), r = j % (4 * 32), nb = r / 32, lane = r % 32;
        int k = kb * 8 + (lane & 3), n = nb * 8 + (lane >> 2);
        g_B1[j] = packtf(comb_1(k, n, Wlv, W011, w01),
                         comb_1(k + 4, n, Wlv, W011, w01));
    } else if (i < WTOT) {
        int j = i - NSZ - V1Z;
        int kb = j / (4 * 32), r = j % (4 * 32), nb = r / 32, lane = r % 32;
        int k = kb * 8 + (lane & 3), n = nb * 8 + (lane >> 2);
        g_B2[j] = packtf(comb_2(k, n, Wlv, W101, w10),
                         comb_2(k + 4, n, Wlv, W101, w10));
    } else {
        int e = i - WTOT;
        if (e < E) {
            int dst = __ldg(eidx + E + e);   // edge_index row 1 = destination
            int pos = atomicAdd(&g_cnt[dst], 1);
            if (pos < CAP) g_list[dst * CAP + pos] = e;
        }
    }
}

// ---------------------------------------------------------------------------
// Kernel 2: atomic-free gather, one float4 chunk per thread, edge-unroll-4.
// ---------------------------------------------------------------------------
__global__ void gather_msg(const float4* __restrict__ em, int N)
{
    int i = blockIdx.x * blockDim.x + threadIdx.x;
    if (i >= N * 40) return;
    int n = i / 40;
    int j = i - n * 40;
    int deg = g_cnt[n];
    if (deg > CAP) deg = CAP;
    const int* lst = g_list + n * CAP;
    float4 s = make_float4(0.f, 0.f, 0.f, 0.f);
    int k = 0;
    for (; k + 4 <= deg; k += 4) {
        int e0 = __ldg(lst + k);
        int e1 = __ldg(lst + k + 1);
        int e2 = __ldg(lst + k + 2);
        int e3 = __ldg(lst + k + 3);
        float4 v0 = __ldcs(em + (size_t)e0 * 40 + j);
        float4 v1 = __ldcs(em + (size_t)e1 * 40 + j);
        float4 v2 = __ldcs(em + (size_t)e2 * 40 + j);
        float4 v3 = __ldcs(em + (size_t)e3 * 40 + j);
        s.x += (v0.x + v1.x) + (v2.x + v3.x);
        s.y += (v0.y + v1.y) + (v2.y + v3.y);
        s.z += (v0.z + v1.z) + (v2.z + v3.z);
        s.w += (v0.w + v1.w) + (v2.w + v3.w);
    }
    if (k + 2 <= deg) {
        int e0 = __ldg(lst + k);
        int e1 = __ldg(lst + k + 1);
        float4 v0 = __ldcs(em + (size_t)e0 * 40 + j);
        float4 v1 = __ldcs(em + (size_t)e1 * 40 + j);
        s.x += v0.x + v1.x; s.y += v0.y + v1.y;
        s.z += v0.z + v1.z; s.w += v0.w + v1.w;
        k += 2;
    }
    if (k < deg) {
        int e = __ldg(lst + k);
        float4 v = __ldcs(em + (size_t)e * 40 + j);
        s.x += v.x; s.y += v.y; s.z += v.z; s.w += v.w;
    }
    reinterpret_cast<float4*>(g_msg)[i] = s;
}

// ---------------------------------------------------------------------------
// Kernel 3: per-node update (m16n8k8 tf32), warp grid = N-half x K-half,
// A fragments via ldmatrix.x4 (1 LDSM replaces 4 LDS.32).
// 128 threads = 4 warps, 16 nodes/CTA, 33 KB smem. (R14 structure.)
// ---------------------------------------------------------------------------
__global__ void __launch_bounds__(128)
node_update(const float* __restrict__ feats,
            const float* __restrict__ attrs,
            float*       __restrict__ out,
            int N)
{
    extern __shared__ __align__(16) float sm[];
    float* sU  = sm;                    // NPC * USTRIDE (reused as sred later)
    float* sAv = sm + NPC * USTRIDE;    // NPC * 3

    const float rs5  = 0.44721359549995794f;  // 1/sqrt(5)
    const float inv3 = 0.5773502691896258f;   // 1/sqrt(3)

    const int t    = threadIdx.x;
    const int base = blockIdx.x * NPC;

    // ---- prologue: build tf32-rounded U (8 threads per node) ----
    {
        int i  = t >> 3;
        int t8 = t & 7;
        int n  = base + i;
        float* u = sU + i * USTRIDE;
        if (n < N) {
            float a0  = __ldg(attrs + n * 4 + 0);
            float av0 = __ldg(attrs + n * 4 + 1);
            float av1 = __ldg(attrs + n * 4 + 2);
            float av2 = __ldg(attrs + n * 4 + 3);
            if (t8 == 0) {
                sAv[i * 3 + 0] = av0; sAv[i * 3 + 1] = av1; sAv[i * 3 + 2] = av2;
                g_cnt[n] = 0;   // reset degree counter for the next run
            }
            const float* mrow = g_msg + (size_t)n * DIM;
            const float* frow = feats + (size_t)n * DIM;
            #pragma unroll
            for (int k = t8; k < 64; k += 8) {
                float ms = mrow[k] * rs5;
                float xs = __ldcs(frow + k);
                u[k]       = tf32f(a0 * ms);
                u[96 + k]  = tf32f(a0 * xs);
                u[192 + k] = tf32f(ms);
                u[256 + k] = tf32f(xs);
            }
            #pragma unroll
            for (int k = t8; k < 32; k += 8) {
                float m0 = mrow[64 + k * 3 + 0] * rs5;
                float m1 = mrow[64 + k * 3 + 1] * rs5;
                float m2 = mrow[64 + k * 3 + 2] * rs5;
                float x0 = __ldcs(frow + 64 + k * 3 + 0);
                float x1 = __ldcs(frow + 64 + k * 3 + 1);
                float x2 = __ldcs(frow + 64 + k * 3 + 2);
                u[64 + k]  = tf32f((m0 * av0 + m1 * av1 + m2 * av2) * inv3);
                u[160 + k] = tf32f((x0 * av0 + x1 * av1 + x2 * av2) * inv3);
                u[320 + k] = tf32f(a0 * m0);
                u[384 + k] = tf32f(a0 * m1);
                u[448 + k] = tf32f(a0 * m2);
                u[352 + k] = tf32f(a0 * x0);
                u[416 + k] = tf32f(a0 * x1);
                u[480 + k] = tf32f(a0 * x2);
            }
        } else {
            #pragma unroll
            for (int k = t8; k < 512; k += 8) u[k] = 0.f;
            if (t8 == 0) { sAv[i*3] = 0.f; sAv[i*3+1] = 0.f; sAv[i*3+2] = 0.f; }
        }
    }
    __syncthreads();

    const int lane = t & 31;
    const int w    = t >> 5;
    const int nh   = w & 1;          // N half (0 or 1)
    const int kh   = w >> 1;         // K half (0 or 1)
    const int gid  = lane >> 2;
    const int tid  = lane & 3;

    // ldmatrix lane address: row = lane&15, word offset 4 for upper matrices
    unsigned aBase = (unsigned)__cvta_generic_to_shared(sU)
                   + (((lane & 15) * USTRIDE + ((lane >> 4) << 2)) << 2);

    // ---- s-path: 6 N-tiles, K-half kb in [12kh, 12kh+12) ----
    float sd[6][4];
    #pragma unroll
    for (int j = 0; j < 6; ++j)
        { sd[j][0]=0.f; sd[j][1]=0.f; sd[j][2]=0.f; sd[j][3]=0.f; }
    #pragma unroll 4
    for (int kk = 0; kk < 12; ++kk) {
        int kb = 12 * kh + kk;
        unsigned a0, a1, a2, a3;
        LDSM4(a0, a1, a2, a3, aBase + ((kb * 8) << 2));
        #pragma unroll
        for (int j = 0; j < 6; ++j) {
            int tile = 2 * nh + (j & 1) + 4 * (j >> 1);
            ull b = __ldg(g_Bs + (kb * 12 + tile) * 32 + lane);
            MMA8(sd[j], a0, a1, a2, a3, b);
        }
    }

    // ---- v1: tiles {2nh, 2nh+1}, K-half kb in [8kh, 8kh+8) ----
    float vd[2][4];
    #pragma unroll
    for (int j = 0; j < 2; ++j)
        { vd[j][0]=0.f; vd[j][1]=0.f; vd[j][2]=0.f; vd[j][3]=0.f; }
    #pragma unroll 4
    for (int kk = 0; kk < 8; ++kk) {
        int kb = 8 * kh + kk;
        unsigned a0, a1, a2, a3;
        LDSM4(a0, a1, a2, a3, aBase + ((192 + kb * 8) << 2));
        #pragma unroll
        for (int j = 0; j < 2; ++j) {
            ull b = __ldg(g_B1 + (kb * 4 + 2 * nh + j) * 32 + lane);
            MMA8(vd[j], a0, a1, a2, a3, b);
        }
    }

    // ---- v2: tiles {2nh, 2nh+1} x 3 channels, K-half kb in [4kh, 4kh+4) ----
    float pd[2][3][4];
    #pragma unroll
    for (int j = 0; j < 2; ++j)
        #pragma unroll
        for (int c = 0; c < 3; ++c)
            { pd[j][c][0]=0.f; pd[j][c][1]=0.f; pd[j][c][2]=0.f; pd[j][c][3]=0.f; }
    #pragma unroll 2
    for (int kk = 0; kk < 4; ++kk) {
        int kb = 4 * kh + kk;
        ull b0 = __ldg(g_B2 + (kb * 4 + 2 * nh) * 32 + lane);
        ull b1 = __ldg(g_B2 + (kb * 4 + 2 * nh + 1) * 32 + lane);
        #pragma unroll
        for (int c = 0; c < 3; ++c) {
            unsigned a0, a1, a2, a3;
            LDSM4(a0, a1, a2, a3, aBase + ((320 + 64 * c + kb * 8) << 2));
            MMA8(pd[0][c], a0, a1, a2, a3, b0);
            MMA8(pd[1][c], a0, a1, a2, a3, b1);
        }
    }

    // ---- cross-warp K reduction: kh=1 -> shared -> kh=0 adds ----
    __syncthreads();
    float* sred = sm + nh * 56 * 32;
    if (kh == 1) {
        #pragma unroll
        for (int j = 0; j < 6; ++j)
            #pragma unroll
            for (int q = 0; q < 4; ++q)
                sred[(j * 4 + q) * 32 + lane] = sd[j][q];
        #pragma unroll
        for (int j = 0; j < 2; ++j)
            #pragma unroll
            for (int q = 0; q < 4; ++q)
                sred[(24 + j * 4 + q) * 32 + lane] = vd[j][q];
        #pragma unroll
        for (int j = 0; j < 2; ++j)
            #pragma unroll
            for (int c = 0; c < 3; ++c)
                #pragma unroll
                for (int q = 0; q < 4; ++q)
                    sred[(32 + (j * 3 + c) * 4 + q) * 32 + lane] = pd[j][c][q];
    }
    __syncthreads();
    if (kh == 1) return;

    #pragma unroll
    for (int j = 0; j < 6; ++j)
        #pragma unroll
        for (int q = 0; q < 4; ++q)
            sd[j][q] += sred[(j * 4 + q) * 32 + lane];
    #pragma unroll
    for (int j = 0; j < 2; ++j)
        #pragma unroll
        for (int q = 0; q < 4; ++q)
            vd[j][q] += sred[(24 + j * 4 + q) * 32 + lane];
    #pragma unroll
    for (int j = 0; j < 2; ++j)
        #pragma unroll
        for (int c = 0; c < 3; ++c)
            #pragma unroll
            for (int q = 0; q < 4; ++q)
                pd[j][c][q] += sred[(32 + (j * 3 + c) * 4 + q) * 32 + lane];

    // ---- epilogue (kh=0 warps): all combining in registers ----
    const int nvalid = N - base;
    #pragma unroll
    for (int r = 0; r < 2; ++r) {
        int slot = gid + 8 * r;
        if (slot < nvalid) {
            float* orow = out + (size_t)(base + slot) * DIM;
            #pragma unroll
            for (int jj = 0; jj < 2; ++jj) {
                float x0 = sd[jj][2*r], x1 = sd[jj][2*r+1];
                float y0 = sd[2+jj][2*r], y1 = sd[2+jj][2*r+1];
                *(float2*)(orow + 8 * (2 * nh + jj) + 2 * tid) =
                    make_float2(x0 / (1.f + __expf(-x0)),
                                x1 / (1.f + __expf(-x1)));
                *(float2*)(orow + 32 + 8 * (2 * nh + jj) + 2 * tid) =
                    make_float2(y0 / (1.f + __expf(-y0)),
                                y1 / (1.f + __expf(-y1)));
            }
            float av0 = sAv[slot * 3 + 0];
            float av1 = sAv[slot * 3 + 1];
            float av2 = sAv[slot * 3 + 2];
            #pragma unroll
            for (int jj = 0; jj < 2; ++jj) {
                float g0 = 1.f / (1.f + __expf(-sd[4+jj][2*r]));
                float g1 = 1.f / (1.f + __expf(-sd[4+jj][2*r+1]));
                float v0 = vd[jj][2*r], v1 = vd[jj][2*r+1];
                float j0c0 = g0 * fmaf(v0, av0, pd[jj][0][2*r]);
                float j0c1 = g0 * fmaf(v0, av1, pd[jj][1][2*r]);
                float j0c2 = g0 * fmaf(v0, av2, pd[jj][2][2*r]);
                float j1c0 = g1 * fmaf(v1, av0, pd[jj][0][2*r+1]);
                float j1c1 = g1 * fmaf(v1, av1, pd[jj][1][2*r+1]);
                float j1c2 = g1 * fmaf(v1, av2, pd[jj][2][2*r+1]);
                float* vout = orow + NS + (8 * (2 * nh + jj) + 2 * tid) * 3;
                *(float2*)(vout + 0) = make_float2(j0c0, j0c1);
                *(float2*)(vout + 2) = make_float2(j0c2, j1c0);
                *(float2*)(vout + 4) = make_float2(j1c1, j1c2);
            }
        }
    }
}

// ---------------------------------------------------------------------------
extern "C" void kernel_launch(void* const* d_in, const int* in_sizes, int n_in,
                              void* d_out, int out_size)
{
    const float* feats = (const float*)d_in[0];
    const float* attrs = (const float*)d_in[1];
    const float* emsg  = (const float*)d_in[2];
    const int*   eidx  = (const int*)  d_in[3];
    const float* w00   = (const float*)d_in[4];
    const float* w01   = (const float*)d_in[5];
    const float* w10   = (const float*)d_in[6];
    const float* w11   = (const float*)d_in[7];
    const float* Wls   = (const float*)d_in[8];
    const float* Wlv   = (const float*)d_in[9];
    const float* W000  = (const float*)d_in[10];
    const float* W110  = (const float*)d_in[11];
    const float* W011  = (const float*)d_in[12];
    const float* W101  = (const float*)d_in[13];

    int N = in_sizes[0] / DIM;
    int E = in_sizes[2] / DIM;

    const int smem_bytes = NPC * USTRIDE * 4 + NPC * 3 * 4;  // 33216
    cudaFuncSetAttribute(node_update,
                         cudaFuncAttributeMaxDynamicSharedMemorySize, smem_bytes);

    // 1. weight packing + edge binning (fused; counters already zero)
    int total1 = 24 * 12 * 32 + 16 * 4 * 32 + 8 * 4 * 32 + E;
    prep_and_bin<<<(total1 + 255) / 256, 256>>>(
        Wls, Wlv, W000, W110, W011, W101, w00, w01, w10, w11, eidx, E);

    // 2. gather (1 chunk/thread, edge-unroll-4)
    int gthreads = N * 40;
    gather_msg<<<(gthreads + 511) / 512, 512>>>((const float4*)emsg, N);

    // 3. node update (also re-zeroes g_cnt for the next run)
    int blocks = (N + NPC - 1) / NPC;
    node_update<<<blocks, 128, smem_bytes>>>(feats, attrs, (float*)d_out, N);
}

// round 17
// speedup vs baseline: 1.1240x; 1.0193x over previous
#include <cuda_runtime.h>
#include <cuda_bf16.h>
#include <cstdint>

#define MAX_N 100000
#define MAX_E 500000
#define DIM     160
#define NS       64
#define NV       32
#define USTRIDE 516   // U row stride (floats); %32==4 -> conflict-free frags
#define CAP      32   // per-node edge-list capacity (Poisson(5): P(>=32)~3e-17)
#define NPC      16   // nodes per CTA (node_update)

typedef unsigned long long ull;

// ---- device scratch (no allocs allowed) ----
// g_cnt is zero-initialized at module load; node_update re-zeroes it each run.
__device__ int g_cnt[MAX_N];                        // per-node degree
__device__ int g_list[MAX_N * CAP];                 // per-node edge ids
__device__ __align__(16) float g_msg[MAX_N * DIM];  // gathered message sums
// Weights pre-packed in m16n8k8 B-fragment order, tf32-rounded.
__device__ __align__(16) ull g_Bs[24 * 12 * 32];   // s-path  K=192, O=96
__device__ __align__(16) ull g_B1[16 * 4 * 32];    // v1      K=128, O=32
__device__ __align__(16) ull g_B2[ 8 * 4 * 32];    // v2      K=64,  O=32

__device__ __forceinline__ unsigned tf32r(float x) {
    unsigned r; asm("cvt.rna.tf32.f32 %0, %1;" : "=r"(r) : "f"(x)); return r;
}
__device__ __forceinline__ ull packtf(float lo, float hi) {
    return (ull)tf32r(lo) | ((ull)tf32r(hi) << 32);
}
__device__ __forceinline__ float tf32f(float x) {
    return __uint_as_float(tf32r(x));
}
__device__ __forceinline__ float4 tf32f4(float a, float b, float c, float d) {
    return make_float4(tf32f(a), tf32f(b), tf32f(c), tf32f(d));
}

#define MMA8(d, a0, a1, a2, a3, bb)                                         \
    asm("mma.sync.aligned.m16n8k8.row.col.f32.tf32.tf32.f32 "               \
        "{%0,%1,%2,%3}, {%4,%5,%6,%7}, {%8,%9}, {%0,%1,%2,%3};"             \
        : "+f"(d[0]), "+f"(d[1]), "+f"(d[2]), "+f"(d[3])                    \
        : "r"(a0), "r"(a1), "r"(a2), "r"(a3),                               \
          "r"((unsigned)(bb)), "r"((unsigned)((bb) >> 32)))

// One LDSM.x4 loads the full 16x8 tf32 A fragment (as 16x16 b16).
#define LDSM4(a0, a1, a2, a3, addr)                                         \
    asm volatile("ldmatrix.sync.aligned.m8n8.x4.shared.b16 "                \
                 "{%0,%1,%2,%3}, [%4];"                                     \
                 : "=r"(a0), "=r"(a1), "=r"(a2), "=r"(a3) : "r"(addr))

// ---------------------------------------------------------------------------
// Combined-weight element generators (fold all norm scalars + tp vectors)
// ---------------------------------------------------------------------------
__device__ __forceinline__ float comb_s(int u, int o,
                                        const float* Wls, const float* W000,
                                        const float* W110, const float* w00,
                                        const float* w11) {
    const float inv_fan = rsqrtf(96.f);
    const float inv2 = rsqrtf(2.f);
    if (u < 64)  return Wls[u * 96 + o] * inv_fan * w00[u];
    if (u < 96)  return Wls[u * 96 + o] * inv_fan * w11[u - 64];
    if (u < 160) return W000[(u - 96) * 96 + o] * inv2 * rsqrtf(64.f);
    return W110[(u - 160) * 96 + o] * inv2 * rsqrtf(32.f);
}
__device__ __forceinline__ float comb_1(int u, int o,
                                        const float* Wlv, const float* W011,
                                        const float* w01) {
    const float inv_fan = rsqrtf(96.f);
    const float inv2 = rsqrtf(2.f);
    if (u < 64) return Wlv[u * 32 + o] * inv_fan * w01[u];
    return W011[(u - 64) * 32 + o] * inv2 * rsqrtf(64.f);
}
__device__ __forceinline__ float comb_2(int u, int o,
                                        const float* Wlv, const float* W101,
                                        const float* w10) {
    const float inv_fan = rsqrtf(96.f);
    const float inv2 = rsqrtf(2.f);
    if (u < 32) return Wlv[(64 + u) * 32 + o] * inv_fan * w10[u];
    return W101[(u - 32) * 32 + o] * inv2 * rsqrtf(32.f);
}

// ---------------------------------------------------------------------------
// Kernel 1: weight packing FUSED with edge binning (independent ranges).
// ---------------------------------------------------------------------------
__global__ void prep_and_bin(const float* __restrict__ Wls,
                             const float* __restrict__ Wlv,
                             const float* __restrict__ W000,
                             const float* __restrict__ W110,
                             const float* __restrict__ W011,
                             const float* __restrict__ W101,
                             const float* __restrict__ w00,
                             const float* __restrict__ w01,
                             const float* __restrict__ w10,
                             const float* __restrict__ w11,
                             const int*   __restrict__ eidx,
                             int E)
{
    int i = blockIdx.x * blockDim.x + threadIdx.x;
    const int NSZ = 24 * 12 * 32;
    const int V1Z = 16 * 4 * 32;
    const int V2Z = 8 * 4 * 32;
    const int WTOT = NSZ + V1Z + V2Z;
    if (i < NSZ) {
        int kb = i / (12 * 32), r = i % (12 * 32), nb = r / 32, lane = r % 32;
        int k = kb * 8 + (lane & 3), n = nb * 8 + (lane >> 2);
        g_Bs[i] = packtf(comb_s(k, n, Wls, W000, W110, w00, w11),
                         comb_s(k + 4, n, Wls, W000, W110, w00, w11));
    } else if (i < NSZ + V1Z) {
        int j = i - NSZ;
        int kb = j / (4 * 32), r = j % (4 * 32), nb = r / 32, lane = r % 32;
        int k = kb * 8 + (lane & 3), n = nb * 8 + (lane >> 2);
        g_B1[j] = packtf(comb_1(k, n, Wlv, W011, w01),
                         comb_1(k + 4, n, Wlv, W011, w01));
    } else if (i < WTOT) {
        int j = i - NSZ - V1Z;
        int kb = j / (4 * 32), r = j % (4 * 32), nb = r / 32, lane = r % 32;
        int k = kb * 8 + (lane & 3), n = nb * 8 + (lane >> 2);
        g_B2[j] = packtf(comb_2(k, n, Wlv, W101, w10),
                         comb_2(k + 4, n, Wlv, W101, w10));
    } else {
        int e = i - WTOT;
        if (e < E) {
            int dst = __ldg(eidx + E + e);   // edge_index row 1 = destination
            int pos = atomicAdd(&g_cnt[dst], 1);
            if (pos < CAP) g_list[dst * CAP + pos] = e;
        }
    }
}

// ---------------------------------------------------------------------------
// Kernel 2: atomic-free gather, one float4 chunk per thread, edge-unroll-4.
// ---------------------------------------------------------------------------
__global__ void gather_msg(const float4* __restrict__ em, int N)
{
    int i = blockIdx.x * blockDim.x + threadIdx.x;
    if (i >= N * 40) return;
    int n = i / 40;
    int j = i - n * 40;
    int deg = g_cnt[n];
    if (deg > CAP) deg = CAP;
    const int* lst = g_list + n * CAP;
    float4 s = make_float4(0.f, 0.f, 0.f, 0.f);
    int k = 0;
    for (; k + 4 <= deg; k += 4) {
        int e0 = __ldg(lst + k);
        int e1 = __ldg(lst + k + 1);
        int e2 = __ldg(lst + k + 2);
        int e3 = __ldg(lst + k + 3);
        float4 v0 = __ldcs(em + (size_t)e0 * 40 + j);
        float4 v1 = __ldcs(em + (size_t)e1 * 40 + j);
        float4 v2 = __ldcs(em + (size_t)e2 * 40 + j);
        float4 v3 = __ldcs(em + (size_t)e3 * 40 + j);
        s.x += (v0.x + v1.x) + (v2.x + v3.x);
        s.y += (v0.y + v1.y) + (v2.y + v3.y);
        s.z += (v0.z + v1.z) + (v2.z + v3.z);
        s.w += (v0.w + v1.w) + (v2.w + v3.w);
    }
    if (k + 2 <= deg) {
        int e0 = __ldg(lst + k);
        int e1 = __ldg(lst + k + 1);
        float4 v0 = __ldcs(em + (size_t)e0 * 40 + j);
        float4 v1 = __ldcs(em + (size_t)e1 * 40 + j);
        s.x += v0.x + v1.x; s.y += v0.y + v1.y;
        s.z += v0.z + v1.z; s.w += v0.w + v1.w;
        k += 2;
    }
    if (k < deg) {
        int e = __ldg(lst + k);
        float4 v = __ldcs(em + (size_t)e * 40 + j);
        s.x += v.x; s.y += v.y; s.z += v.z; s.w += v.w;
    }
    reinterpret_cast<float4*>(g_msg)[i] = s;
}

// ---------------------------------------------------------------------------
// Kernel 3: per-node update (m16n8k8 tf32), warp grid = N-half x K-half,
// A fragments via ldmatrix.x4; prologue vectorized (float4 LDG + STS.128).
// 128 threads = 4 warps, 16 nodes/CTA, 33 KB smem.
// ---------------------------------------------------------------------------
__global__ void __launch_bounds__(128)
node_update(const float* __restrict__ feats,
            const float* __restrict__ attrs,
            float*       __restrict__ out,
            int N)
{
    extern __shared__ __align__(16) float sm[];
    float* sU  = sm;                    // NPC * USTRIDE (reused as sred later)
    float* sAv = sm + NPC * USTRIDE;    // NPC * 3

    const float rs5  = 0.44721359549995794f;  // 1/sqrt(5)
    const float inv3 = 0.5773502691896258f;   // 1/sqrt(3)

    const int t    = threadIdx.x;
    const int base = blockIdx.x * NPC;

    // ---- prologue: build tf32-rounded U (8 threads per node) ----
    {
        int i  = t >> 3;
        int t8 = t & 7;
        int n  = base + i;
        float* u = sU + i * USTRIDE;
        if (n < N) {
            float a0  = __ldg(attrs + n * 4 + 0);
            float av0 = __ldg(attrs + n * 4 + 1);
            float av1 = __ldg(attrs + n * 4 + 2);
            float av2 = __ldg(attrs + n * 4 + 3);
            if (t8 == 0) {
                sAv[i * 3 + 0] = av0; sAv[i * 3 + 1] = av1; sAv[i * 3 + 2] = av2;
                g_cnt[n] = 0;   // reset degree counter for the next run
            }
            const float* mrow = g_msg + (size_t)n * DIM;
            const float* frow = feats + (size_t)n * DIM;
            // scalar part k=0..63: float4 per thread, coalesced 128B per q
            #pragma unroll
            for (int q = 0; q < 2; ++q) {
                int k = q * 32 + t8 * 4;
                float4 mm = *(const float4*)(mrow + k);
                float4 xx = __ldcs((const float4*)(frow + k));
                float ms0 = mm.x * rs5, ms1 = mm.y * rs5;
                float ms2 = mm.z * rs5, ms3 = mm.w * rs5;
                *(float4*)(u + k) =
                    tf32f4(a0 * ms0, a0 * ms1, a0 * ms2, a0 * ms3);
                *(float4*)(u + 96 + k) =
                    tf32f4(a0 * xx.x, a0 * xx.y, a0 * xx.z, a0 * xx.w);
                *(float4*)(u + 192 + k) = tf32f4(ms0, ms1, ms2, ms3);
                *(float4*)(u + 256 + k) =
                    tf32f4(xx.x, xx.y, xx.z, xx.w);
            }
            // vector part (stride-3 layout): scalar
            #pragma unroll
            for (int k = t8; k < 32; k += 8) {
                float m0 = mrow[64 + k * 3 + 0] * rs5;
                float m1 = mrow[64 + k * 3 + 1] * rs5;
                float m2 = mrow[64 + k * 3 + 2] * rs5;
                float x0 = __ldcs(frow + 64 + k * 3 + 0);
                float x1 = __ldcs(frow + 64 + k * 3 + 1);
                float x2 = __ldcs(frow + 64 + k * 3 + 2);
                u[64 + k]  = tf32f((m0 * av0 + m1 * av1 + m2 * av2) * inv3);
                u[160 + k] = tf32f((x0 * av0 + x1 * av1 + x2 * av2) * inv3);
                u[320 + k] = tf32f(a0 * m0);
                u[384 + k] = tf32f(a0 * m1);
                u[448 + k] = tf32f(a0 * m2);
                u[352 + k] = tf32f(a0 * x0);
                u[416 + k] = tf32f(a0 * x1);
                u[480 + k] = tf32f(a0 * x2);
            }
        } else {
            #pragma unroll
            for (int k = t8 * 4; k < 512; k += 32)
                *(float4*)(u + k) = make_float4(0.f, 0.f, 0.f, 0.f);
            if (t8 == 0) { sAv[i*3] = 0.f; sAv[i*3+1] = 0.f; sAv[i*3+2] = 0.f; }
        }
    }
    __syncthreads();

    const int lane = t & 31;
    const int w    = t >> 5;
    const int nh   = w & 1;          // N half (0 or 1)
    const int kh   = w >> 1;         // K half (0 or 1)
    const int gid  = lane >> 2;
    const int tid  = lane & 3;

    // ldmatrix lane address: row = lane&15, word offset 4 for upper matrices
    unsigned aBase = (unsigned)__cvta_generic_to_shared(sU)
                   + (((lane & 15) * USTRIDE + ((lane >> 4) << 2)) << 2);

    // ---- s-path: 6 N-tiles, K-half kb in [12kh, 12kh+12) ----
    float sd[6][4];
    #pragma unroll
    for (int j = 0; j < 6; ++j)
        { sd[j][0]=0.f; sd[j][1]=0.f; sd[j][2]=0.f; sd[j][3]=0.f; }
    #pragma unroll 4
    for (int kk = 0; kk < 12; ++kk) {
        int kb = 12 * kh + kk;
        unsigned a0, a1, a2, a3;
        LDSM4(a0, a1, a2, a3, aBase + ((kb * 8) << 2));
        #pragma unroll
        for (int j = 0; j < 6; ++j) {
            int tile = 2 * nh + (j & 1) + 4 * (j >> 1);
            ull b = __ldg(g_Bs + (kb * 12 + tile) * 32 + lane);
            MMA8(sd[j], a0, a1, a2, a3, b);
        }
    }

    // ---- v1: tiles {2nh, 2nh+1}, K-half kb in [8kh, 8kh+8) ----
    float vd[2][4];
    #pragma unroll
    for (int j = 0; j < 2; ++j)
        { vd[j][0]=0.f; vd[j][1]=0.f; vd[j][2]=0.f; vd[j][3]=0.f; }
    #pragma unroll 4
    for (int kk = 0; kk < 8; ++kk) {
        int kb = 8 * kh + kk;
        unsigned a0, a1, a2, a3;
        LDSM4(a0, a1, a2, a3, aBase + ((192 + kb * 8) << 2));
        #pragma unroll
        for (int j = 0; j < 2; ++j) {
            ull b = __ldg(g_B1 + (kb * 4 + 2 * nh + j) * 32 + lane);
            MMA8(vd[j], a0, a1, a2, a3, b);
        }
    }

    // ---- v2: tiles {2nh, 2nh+1} x 3 channels, K-half kb in [4kh, 4kh+4) ----
    float pd[2][3][4];
    #pragma unroll
    for (int j = 0; j < 2; ++j)
        #pragma unroll
        for (int c = 0; c < 3; ++c)
            { pd[j][c][0]=0.f; pd[j][c][1]=0.f; pd[j][c][2]=0.f; pd[j][c][3]=0.f; }
    #pragma unroll 2
    for (int kk = 0; kk < 4; ++kk) {
        int kb = 4 * kh + kk;
        ull b0 = __ldg(g_B2 + (kb * 4 + 2 * nh) * 32 + lane);
        ull b1 = __ldg(g_B2 + (kb * 4 + 2 * nh + 1) * 32 + lane);
        #pragma unroll
        for (int c = 0; c < 3; ++c) {
            unsigned a0, a1, a2, a3;
            LDSM4(a0, a1, a2, a3, aBase + ((320 + 64 * c + kb * 8) << 2));
            MMA8(pd[0][c], a0, a1, a2, a3, b0);
            MMA8(pd[1][c], a0, a1, a2, a3, b1);
        }
    }

    // ---- cross-warp K reduction: kh=1 -> shared -> kh=0 adds ----
    __syncthreads();
    float* sred = sm + nh * 56 * 32;
    if (kh == 1) {
        #pragma unroll
        for (int j = 0; j < 6; ++j)
            #pragma unroll
            for (int q = 0; q < 4; ++q)
                sred[(j * 4 + q) * 32 + lane] = sd[j][q];
        #pragma unroll
        for (int j = 0; j < 2; ++j)
            #pragma unroll
            for (int q = 0; q < 4; ++q)
                sred[(24 + j * 4 + q) * 32 + lane] = vd[j][q];
        #pragma unroll
        for (int j = 0; j < 2; ++j)
            #pragma unroll
            for (int c = 0; c < 3; ++c)
                #pragma unroll
                for (int q = 0; q < 4; ++q)
                    sred[(32 + (j * 3 + c) * 4 + q) * 32 + lane] = pd[j][c][q];
    }
    __syncthreads();
    if (kh == 1) return;

    #pragma unroll
    for (int j = 0; j < 6; ++j)
        #pragma unroll
        for (int q = 0; q < 4; ++q)
            sd[j][q] += sred[(j * 4 + q) * 32 + lane];
    #pragma unroll
    for (int j = 0; j < 2; ++j)
        #pragma unroll
        for (int q = 0; q < 4; ++q)
            vd[j][q] += sred[(24 + j * 4 + q) * 32 + lane];
    #pragma unroll
    for (int j = 0; j < 2; ++j)
        #pragma unroll
        for (int c = 0; c < 3; ++c)
            #pragma unroll
            for (int q = 0; q < 4; ++q)
                pd[j][c][q] += sred[(32 + (j * 3 + c) * 4 + q) * 32 + lane];

    // ---- epilogue (kh=0 warps): all combining in registers ----
    const int nvalid = N - base;
    #pragma unroll
    for (int r = 0; r < 2; ++r) {
        int slot = gid + 8 * r;
        if (slot < nvalid) {
            float* orow = out + (size_t)(base + slot) * DIM;
            #pragma unroll
            for (int jj = 0; jj < 2; ++jj) {
                float x0 = sd[jj][2*r], x1 = sd[jj][2*r+1];
                float y0 = sd[2+jj][2*r], y1 = sd[2+jj][2*r+1];
                *(float2*)(orow + 8 * (2 * nh + jj) + 2 * tid) =
                    make_float2(x0 / (1.f + __expf(-x0)),
                                x1 / (1.f + __expf(-x1)));
                *(float2*)(orow + 32 + 8 * (2 * nh + jj) + 2 * tid) =
                    make_float2(y0 / (1.f + __expf(-y0)),
                                y1 / (1.f + __expf(-y1)));
            }
            float av0 = sAv[slot * 3 + 0];
            float av1 = sAv[slot * 3 + 1];
            float av2 = sAv[slot * 3 + 2];
            #pragma unroll
            for (int jj = 0; jj < 2; ++jj) {
                float g0 = 1.f / (1.f + __expf(-sd[4+jj][2*r]));
                float g1 = 1.f / (1.f + __expf(-sd[4+jj][2*r+1]));
                float v0 = vd[jj][2*r], v1 = vd[jj][2*r+1];
                float j0c0 = g0 * fmaf(v0, av0, pd[jj][0][2*r]);
                float j0c1 = g0 * fmaf(v0, av1, pd[jj][1][2*r]);
                float j0c2 = g0 * fmaf(v0, av2, pd[jj][2][2*r]);
                float j1c0 = g1 * fmaf(v1, av0, pd[jj][0][2*r+1]);
                float j1c1 = g1 * fmaf(v1, av1, pd[jj][1][2*r+1]);
                float j1c2 = g1 * fmaf(v1, av2, pd[jj][2][2*r+1]);
                float* vout = orow + NS + (8 * (2 * nh + jj) + 2 * tid) * 3;
                *(float2*)(vout + 0) = make_float2(j0c0, j0c1);
                *(float2*)(vout + 2) = make_float2(j0c2, j1c0);
                *(float2*)(vout + 4) = make_float2(j1c1, j1c2);
            }
        }
    }
}

// ---------------------------------------------------------------------------
extern "C" void kernel_launch(void* const* d_in, const int* in_sizes, int n_in,
                              void* d_out, int out_size)
{
    const float* feats = (const float*)d_in[0];
    const float* attrs = (const float*)d_in[1];
    const float* emsg  = (const float*)d_in[2];
    const int*   eidx  = (const int*)  d_in[3];
    const float* w00   = (const float*)d_in[4];
    const float* w01   = (const float*)d_in[5];
    const float* w10   = (const float*)d_in[6];
    const float* w11   = (const float*)d_in[7];
    const float* Wls   = (const float*)d_in[8];
    const float* Wlv   = (const float*)d_in[9];
    const float* W000  = (const float*)d_in[10];
    const float* W110  = (const float*)d_in[11];
    const float* W011  = (const float*)d_in[12];
    const float* W101  = (const float*)d_in[13];

    int N = in_sizes[0] / DIM;
    int E = in_sizes[2] / DIM;

    const int smem_bytes = NPC * USTRIDE * 4 + NPC * 3 * 4;  // 33216
    cudaFuncSetAttribute(node_update,
                         cudaFuncAttributeMaxDynamicSharedMemorySize, smem_bytes);

    // 1. weight packing + edge binning (fused; counters already zero)
    int total1 = 24 * 12 * 32 + 16 * 4 * 32 + 8 * 4 * 32 + E;
    prep_and_bin<<<(total1 + 255) / 256, 256>>>(
        Wls, Wlv, W000, W110, W011, W101, w00, w01, w10, w11, eidx, E);

    // 2. gather (1 chunk/thread, edge-unroll-4)
    int gthreads = N * 40;
    gather_msg<<<(gthreads + 511) / 512, 512>>>((const float4*)emsg, N);

    // 3. node update (also re-zeroes g_cnt for the next run)
    int blocks = (N + NPC - 1) / NPC;
    node_update<<<blocks, 128, smem_bytes>>>(feats, attrs, (float*)d_out, N);
}